// round 15
// baseline (speedup 1.0000x reference)
#include <cuda_runtime.h>
#include <math.h>

#define BB 2
#define C  19
#define H  128
#define W  128
#define CH 320
#define CG 32
#define HW (H*W)
#define NSIM_BLK (BB*CG)           // 64 simtab blocks (one coarse row each)
#define NPIX_BLK 256               // 256 pixel blocks (one image row each)
#define NBLK (NSIM_BLK + NPIX_BLK)
#define F32_FLUSH_THRESH 1.1754943508222875e-38   // FLT_MIN: emulate reference FTZ exp

// ---------------- scratch (__device__ globals; no allocation) ----------------
__device__ float    g_Sd[BB * CG * CG * 5]; // per coarse cell: E,SW,S,SE sims + oob sim
__device__ double   g_acc[2];
__device__ int      g_nmask;
__device__ unsigned g_done  = 0;            // pixel finalize ticket (wraps -> replay-safe)
__device__ unsigned g_scnt  = 0;            // simtab completion count (wraps -> replay-safe)
__device__ unsigned g_sflag = 0;            // sim table ready flag (reset by ticket winner)

__global__ void __launch_bounds__(256) mono_k(const float* __restrict__ logits,
                                              const float* __restrict__ x_ema,
                                              float* __restrict__ out) {
    __shared__ float4 rows[3][W * 5];       // prob rows i-2, i, i+2 (30720 B)
    __shared__ float  s_sim[W][9];
    __shared__ float  s_cp[W][9];
    __shared__ float  s_cn[W][9];
    __shared__ float  sr0[8], sr1[8];
    __shared__ int    sr2[8];

    int blk = blockIdx.x;
    int t   = threadIdx.x;

    if (blk < NSIM_BLK) {
        // ================= producer: directed coarse-cell sim table ==========
        if (blk == 0 && t == 0) { g_acc[0] = 0.0; g_acc[1] = 0.0; g_nmask = 0; }

        int b  = blk >> 5, ci = blk & 31;
        __shared__ float red[4][32][5];
        if (t < 128) {
            int g = t >> 5, lane = t & 31;        // lane == cj
            const float* xb = x_ema + ((size_t)(b * CH) * CG + ci) * CG + lane;
            bool has_s = (ci < CG - 1);
            float a0 = 0.f, a1 = 0.f, a2 = 0.f, a3 = 0.f, a4 = 0.f;
#pragma unroll 4
            for (int ch = g; ch < CH; ch += 4) {
                float c  = xb[(size_t)ch * (CG * CG)];
                float sv = has_s ? xb[(size_t)ch * (CG * CG) + CG] : 0.f;
                float nE = __shfl_down_sync(0xffffffffu, c,  1);
                float sW = __shfl_up_sync  (0xffffffffu, sv, 1);
                float sE = __shfl_down_sync(0xffffffffu, sv, 1);
                float d0 = nE - c, d1 = sW - c, d2 = sv - c, d3 = sE - c;
                a0 += d0 * d0; a1 += d1 * d1; a2 += d2 * d2; a3 += d3 * d3; a4 += c * c;
            }
            red[g][lane][0] = a0; red[g][lane][1] = a1; red[g][lane][2] = a2;
            red[g][lane][3] = a3; red[g][lane][4] = a4;
        }
        __syncthreads();
        if (t < 128) {
            // threads cover e=0..3 (one per warp); warp 0 also writes e=4.
            int cj = t & 31, e = t >> 5;
            float* cell_out = g_Sd + (size_t)((b * CG + ci) * CG + cj) * 5;
            float s = red[0][cj][e] + red[1][cj][e] + red[2][cj][e] + red[3][cj][e];
            double tt = exp(-(double)s * 0.25);      // FTZ-immune double exp
            if (tt < F32_FLUSH_THRESH) tt = 0.0;     // emulate reference FTZ
            cell_out[e] = (float)tt;
            if (e == 0) {
                float s4 = red[0][cj][4] + red[1][cj][4] + red[2][cj][4] + red[3][cj][4];
                double t4 = exp(-(double)s4 * 0.25);
                if (t4 < F32_FLUSH_THRESH) t4 = 0.0;
                cell_out[4] = (float)t4;
            }
            __threadfence();                         // publish this thread's g_Sd writes
        }
        __syncthreads();
        if (t == 0) {
            unsigned old = atomicInc(&g_scnt, NSIM_BLK - 1);   // wraps -> replay-safe
            if (old == NSIM_BLK - 1) atomicExch(&g_sflag, 1u); // last producer signals
        }
        return;
    }

    // ================= consumer: softmax-in-smem + per-pixel loss ============
    int pb = blk - NSIM_BLK;
    int b = pb >> 7, i = pb & 127;
    int j    = t & 127;
    int half = t >> 7;
    int ci = i >> 2, cj = j >> 2;

    bool msk = x_ema[(size_t)b * CH * CG * CG + ci * CG + cj] > 0.f;

    // ---- Phase A: softmax for rows i-2, i, i+2 into smem (overlaps simtab) ----
    for (int task = t; task < 384; task += 256) {
        int r  = task >> 7;          // 0,1,2 -> rows i-2, i, i+2
        int jj = task & 127;
        int ni = i + (r - 1) * 2;
        if (ni >= 0 && ni < H) {
            const float* base = logits + (size_t)b * C * HW + ni * W + jj;
            float v[C];
            float m = -INFINITY;
#pragma unroll
            for (int c = 0; c < C; c++) { v[c] = base[c * HW]; m = fmaxf(m, v[c]); }
            float s = 0.f;
#pragma unroll
            for (int c = 0; c < C; c++) { v[c] = expf(v[c] - m); s += v[c]; }
            float inv = 1.f / s;
            float4* o = &rows[r][jj * 5];
            o[0] = make_float4(v[0] * inv,  v[1] * inv,  v[2] * inv,  v[3] * inv);
            o[1] = make_float4(v[4] * inv,  v[5] * inv,  v[6] * inv,  v[7] * inv);
            o[2] = make_float4(v[8] * inv,  v[9] * inv,  v[10] * inv, v[11] * inv);
            o[3] = make_float4(v[12] * inv, v[13] * inv, v[14] * inv, v[15] * inv);
            o[4] = make_float4(v[16] * inv, v[17] * inv, v[18] * inv, 0.f);  // zero pad
        }
    }

    // ---- wait for sim table (one-way flag; producers long done by now) ----
    if (t == 0) {
        while (*(volatile unsigned*)&g_sflag == 0u) { __nanosleep(32); }
    }
    __syncthreads();
    __threadfence();   // order g_Sd reads after flag observation

    // ---- Phase B: per-pixel neighbor dots, split across the two halves ----
    float4 p4[5];
    float sum_p = 0.f;
#pragma unroll
    for (int r = 0; r < 5; r++) {
        p4[r] = rows[1][j * 5 + r];
        sum_p += p4[r].x; sum_p += p4[r].y; sum_p += p4[r].z; sum_p += p4[r].w;
    }

    const float* Sb = g_Sd + (size_t)b * CG * CG * 5;
    float sim_oob = Sb[(ci * CG + cj) * 5 + 4];

    int k_lo = half ? 5 : 0;
    int k_hi = half ? 9 : 5;
#pragma unroll
    for (int k = 0; k < 9; k++) {
        if (k < k_lo || k >= k_hi) continue;
        int a  = k / 3, b2 = k % 3;
        int ni = i + (a - 1) * 2;
        int nj = j + (b2 - 1) * 2;
        float sv, cpos, cneg;
        if (ni < 0 || ni >= H || nj < 0 || nj >= W) {
            sv = sim_oob; cpos = 0.f; cneg = 0.f;
        } else {
            const float4* Q4 = &rows[a][nj * 5];
            float cpv = 0.f, sq = 0.f;
#pragma unroll
            for (int r = 0; r < 5; r++) {
                float4 q = Q4[r];
                cpv += p4[r].x * q.x; sq += q.x;
                cpv += p4[r].y * q.y; sq += q.y;
                cpv += p4[r].z * q.z; sq += q.z;
                cpv += p4[r].w * q.w; sq += q.w;
            }
            cpos = cpv;
            cneg = sum_p * sq - cpv;
            int dci = (ni >> 2) - ci;
            int dcj = (nj >> 2) - cj;
            if ((dci | dcj) == 0)      sv = 1.0f;
            else if (dci < 0)          sv = Sb[((ci - 1) * CG + cj + dcj) * 5 + (2 - dcj)];
            else if (dci > 0)          sv = Sb[(ci * CG + cj) * 5 + (2 + dcj)];
            else if (dcj > 0)          sv = Sb[(ci * CG + cj) * 5 + 0];
            else                       sv = Sb[(ci * CG + cj - 1) * 5 + 0];
        }
        s_sim[j][k] = sv; s_cp[j][k] = cpos; s_cn[j][k] = cneg;
    }
    __syncthreads();

    // ---- Phase C: selections (half 0 = top-5, half 1 = bottom-4) ----
    float mlp = 0.f, mln = 0.f;
    int   mc  = 0;
    if (half == 0) {
        float sim[9], cp[9];
#pragma unroll
        for (int k = 0; k < 9; k++) { sim[k] = s_sim[j][k]; cp[k] = s_cp[j][k]; }
        float lpos = 0.f;
        bool used[9];
#pragma unroll
        for (int k = 0; k < 9; k++) used[k] = false;
#pragma unroll
        for (int tt = 0; tt < 5; tt++) {
            float bv = -1.f, bcp = 0.f; int sel = -1;
#pragma unroll
            for (int k = 0; k < 9; k++)
                if (!used[k] && sim[k] > bv) { bv = sim[k]; bcp = cp[k]; sel = k; }
#pragma unroll
            for (int k = 0; k < 9; k++) used[k] = used[k] || (k == sel);
            lpos += bv * (-bcp);
        }
        mlp = msk ? lpos : 0.f;
        mc  = msk ? 1 : 0;
    } else {
        float sim[9], cn[9];
#pragma unroll
        for (int k = 0; k < 9; k++) { sim[k] = s_sim[j][k]; cn[k] = s_cn[j][k]; }
        float lneg = 0.f;
        bool used[9];
#pragma unroll
        for (int k = 0; k < 9; k++) used[k] = false;
#pragma unroll
        for (int tt = 0; tt < 4; tt++) {
            float bv = 2.f, bcn = 0.f; int sel = -1;
#pragma unroll
            for (int k = 0; k < 9; k++)
                if (!used[k] && sim[k] < bv) { bv = sim[k]; bcn = cn[k]; sel = k; }
#pragma unroll
            for (int k = 0; k < 9; k++) used[k] = used[k] || (k == sel);
            lneg += (1.f - bv) * (-bcn);
        }
        mln = msk ? lneg : 0.f;
    }

    // ---- block reduce (8 warps) + atomic/ticket finalize ----
#pragma unroll
    for (int off = 16; off; off >>= 1) {
        mlp += __shfl_down_sync(0xffffffffu, mlp, off);
        mln += __shfl_down_sync(0xffffffffu, mln, off);
        mc  += __shfl_down_sync(0xffffffffu, mc,  off);
    }
    int lane = t & 31, wid = t >> 5;
    if (lane == 0) { sr0[wid] = mlp; sr1[wid] = mln; sr2[wid] = mc; }
    __syncthreads();
    if (t == 0) {
        double a0 = 0.0, a1 = 0.0; int a2 = 0;
#pragma unroll
        for (int w = 0; w < 8; w++) { a0 += sr0[w]; a1 += sr1[w]; a2 += sr2[w]; }
        atomicAdd(&g_acc[0], a0);
        atomicAdd(&g_acc[1], a1);
        atomicAdd(&g_nmask, a2);
        __threadfence();
        unsigned old = atomicInc(&g_done, NPIX_BLK - 1);   // wraps -> replay-safe
        if (old == NPIX_BLK - 1) {
            double p0 = atomicAdd(&g_acc[0], 0.0);
            double p1 = atomicAdd(&g_acc[1], 0.0);
            int    nm = atomicAdd(&g_nmask, 0);
            out[0] = (float)p0 / ((float)nm * 5.0f);   // W_POS = 1
            out[1] = (float)p1 / ((float)nm * 4.0f);   // W_NEG = 1
            __threadfence();
            *(volatile unsigned*)&g_sflag = 0u;        // reset for next graph replay
        }
    }
}

// ---------------- launch: ONE kernel ----------------
extern "C" void kernel_launch(void* const* d_in, const int* in_sizes, int n_in,
                              void* d_out, int out_size) {
    const float* logits = (const float*)d_in[0];  // (2,19,128,128)
    const float* x_ema  = (const float*)d_in[1];  // (2,320,32,32)
    // d_in[2] = img_trg, unused by the reference.
    float* out = (float*)d_out;

    mono_k<<<NBLK, 256>>>(logits, x_ema, out);
}

// round 17
// speedup vs baseline: 1.0017x; 1.0017x over previous
#include <cuda_runtime.h>
#include <math.h>

#define BB 2
#define C  19
#define H  128
#define W  128
#define CH 320
#define CG 32
#define HW (H*W)
#define NBLK 256                   // one block per image row; fully independent
#define F32_FLUSH_THRESH 1.1754943508222875e-38   // FLT_MIN: emulate reference FTZ exp

// ---------------- scratch (__device__ globals; no allocation) ----------------
__device__ double   g_acc[2] = {0.0, 0.0};  // reset by ticket winner each launch
__device__ int      g_nmask  = 0;
__device__ unsigned g_done   = 0;           // ticket (wraps -> replay-safe)

__global__ void __launch_bounds__(128) mono_k(const float* __restrict__ logits,
                                              const float* __restrict__ x_ema,
                                              float* __restrict__ out) {
    __shared__ float4 rows[3][W * 5];   // softmax rows i-2, i, i+2 (30720 B)
    __shared__ float  red[4][32][8];    // per-warp sim accumulators (4 KB)
    __shared__ float  tab[32][8];       // local sim table: e0..e4 cur row, e5..e7 prev row
    __shared__ float  sr0[4], sr1[4];
    __shared__ int    sr2[4];

    int blk = blockIdx.x;
    int t   = threadIdx.x;
    int b = blk >> 7, i = blk & 127;
    int j = t;                          // one pixel per thread
    int ci = i >> 2, cj = j >> 2;

    bool msk = x_ema[(size_t)b * CH * CG * CG + ci * CG + cj] > 0.f;

    // ===== Phase A: softmax for rows i-2, i, i+2 into smem (col j, 3 rows) =====
    for (int task = t; task < 384; task += 128) {
        int r  = task >> 7;             // 0,1,2 -> rows i-2, i, i+2
        int ni = i + (r - 1) * 2;
        if (ni >= 0 && ni < H) {
            const float* base = logits + (size_t)b * C * HW + ni * W + j;
            float v[C];
            float m = -INFINITY;
#pragma unroll
            for (int c = 0; c < C; c++) { v[c] = base[c * HW]; m = fmaxf(m, v[c]); }
            float s = 0.f;
#pragma unroll
            for (int c = 0; c < C; c++) { v[c] = expf(v[c] - m); s += v[c]; }
            float inv = 1.f / s;
            float4* o = &rows[r][j * 5];
            o[0] = make_float4(v[0] * inv,  v[1] * inv,  v[2] * inv,  v[3] * inv);
            o[1] = make_float4(v[4] * inv,  v[5] * inv,  v[6] * inv,  v[7] * inv);
            o[2] = make_float4(v[8] * inv,  v[9] * inv,  v[10] * inv, v[11] * inv);
            o[3] = make_float4(v[12] * inv, v[13] * inv, v[14] * inv, v[15] * inv);
            o[4] = make_float4(v[16] * inv, v[17] * inv, v[18] * inv, 0.f);  // zero pad
        }
    }

    // ===== Phase B: LOCAL sim table for coarse rows ci-1/ci/ci+1 ==============
    // 4 warps split channels mod 4 (validated order); lane = coarse cell cj.
    // Entries: 0..3 = cur-row E,SW,S,SE; 4 = ||f||^2; 5..7 = prev-row SW,S,SE.
    // Edge-lane shuffle garbage lands only in entries never read by Phase C.
    {
        int g = t >> 5, lane = t & 31;
        const float* xb = x_ema + (size_t)b * CH * CG * CG + ci * CG + lane;
        bool has_p = (ci > 0);
        bool has_s = (ci < CG - 1);
        float a0 = 0.f, a1 = 0.f, a2 = 0.f, a3 = 0.f, a4 = 0.f,
              a5 = 0.f, a6 = 0.f, a7 = 0.f;
#pragma unroll 4
        for (int ch = g; ch < CH; ch += 4) {
            const float* xc = xb + (size_t)ch * (CG * CG);
            float c  = xc[0];
            float sv = has_s ? xc[CG]  : 0.f;
            float pv = has_p ? xc[-CG] : 0.f;
            float cE = __shfl_down_sync(0xffffffffu, c,  1);
            float cW = __shfl_up_sync  (0xffffffffu, c,  1);
            float sW = __shfl_up_sync  (0xffffffffu, sv, 1);
            float sE = __shfl_down_sync(0xffffffffu, sv, 1);
            float d0 = cE - c,  d1 = sW - c,  d2 = sv - c,  d3 = sE - c;
            float d5 = cW - pv, d6 = c - pv,  d7 = cE - pv;
            a0 += d0 * d0; a1 += d1 * d1; a2 += d2 * d2; a3 += d3 * d3;
            a4 += c * c;
            a5 += d5 * d5; a6 += d6 * d6; a7 += d7 * d7;
        }
        red[g][lane][0] = a0; red[g][lane][1] = a1; red[g][lane][2] = a2;
        red[g][lane][3] = a3; red[g][lane][4] = a4; red[g][lane][5] = a5;
        red[g][lane][6] = a6; red[g][lane][7] = a7;
    }
    __syncthreads();
    {
        // 256 (cell, entry) pairs over 128 threads (2 each)
        for (int pair = t; pair < 256; pair += 128) {
            int cell = pair & 31, e = pair >> 5;
            float s = red[0][cell][e] + red[1][cell][e] + red[2][cell][e] + red[3][cell][e];
            double tt = exp(-(double)s * 0.25);      // FTZ-immune double exp
            if (tt < F32_FLUSH_THRESH) tt = 0.0;     // emulate reference FTZ
            tab[cell][e] = (float)tt;
        }
    }
    __syncthreads();

    // ===== Phase C: per-pixel loss (R8 path, sims from local tab) =============
    float4 p4[5];
    float sum_p = 0.f;
#pragma unroll
    for (int r = 0; r < 5; r++) {
        p4[r] = rows[1][j * 5 + r];
        sum_p += p4[r].x; sum_p += p4[r].y; sum_p += p4[r].z; sum_p += p4[r].w;
    }

    float sim_oob = tab[cj][4];

    float sim[9], cp[9], cn[9];
#pragma unroll
    for (int k = 0; k < 9; k++) {
        int a  = k / 3, b2 = k % 3;
        int ni = i + (a - 1) * 2;
        int nj = j + (b2 - 1) * 2;
        if (ni < 0 || ni >= H || nj < 0 || nj >= W) {
            sim[k] = sim_oob; cp[k] = 0.f; cn[k] = 0.f;
        } else {
            const float4* Q4 = &rows[a][nj * 5];
            float cpos = 0.f, sq = 0.f;
#pragma unroll
            for (int r = 0; r < 5; r++) {
                float4 q = Q4[r];
                cpos += p4[r].x * q.x; sq += q.x;
                cpos += p4[r].y * q.y; sq += q.y;
                cpos += p4[r].z * q.z; sq += q.z;
                cpos += p4[r].w * q.w; sq += q.w;
            }
            cp[k] = cpos;
            cn[k] = sum_p * sq - cpos;
            int dci = (ni >> 2) - ci;
            int dcj = (nj >> 2) - cj;
            float sv;
            if ((dci | dcj) == 0)      sv = 1.0f;
            else if (dci < 0)          sv = tab[cj + dcj][4 + (2 - dcj)];  // prev-row entries
            else if (dci > 0)          sv = tab[cj][2 + dcj];              // cur-row south
            else if (dcj > 0)          sv = tab[cj][0];                    // cur-row E
            else                       sv = tab[cj - 1][0];
            sim[k] = sv;
        }
    }

    // top-5 largest sims (stable: lowest index wins ties, like jax top_k)
    float lpos = 0.f;
    {
        bool used[9];
#pragma unroll
        for (int k = 0; k < 9; k++) used[k] = false;
#pragma unroll
        for (int tt = 0; tt < 5; tt++) {
            float bv = -1.f, bcp = 0.f; int sel = -1;
#pragma unroll
            for (int k = 0; k < 9; k++)
                if (!used[k] && sim[k] > bv) { bv = sim[k]; bcp = cp[k]; sel = k; }
#pragma unroll
            for (int k = 0; k < 9; k++) used[k] = used[k] || (k == sel);
            lpos += bv * (-bcp);
        }
    }
    // bottom-4 sims (stable lowest-index ties, like top_k(-sim))
    float lneg = 0.f;
    {
        bool used[9];
#pragma unroll
        for (int k = 0; k < 9; k++) used[k] = false;
#pragma unroll
        for (int tt = 0; tt < 4; tt++) {
            float bv = 2.f, bcn = 0.f; int sel = -1;
#pragma unroll
            for (int k = 0; k < 9; k++)
                if (!used[k] && sim[k] < bv) { bv = sim[k]; bcn = cn[k]; sel = k; }
#pragma unroll
            for (int k = 0; k < 9; k++) used[k] = used[k] || (k == sel);
            lneg += (1.f - bv) * (-bcn);
        }
    }

    float mlp = msk ? lpos : 0.f;
    float mln = msk ? lneg : 0.f;
    int   mc  = msk ? 1 : 0;

    // ===== Phase D: block reduce (4 warps) + atomic/ticket finalize ===========
#pragma unroll
    for (int off = 16; off; off >>= 1) {
        mlp += __shfl_down_sync(0xffffffffu, mlp, off);
        mln += __shfl_down_sync(0xffffffffu, mln, off);
        mc  += __shfl_down_sync(0xffffffffu, mc,  off);
    }
    int lane = t & 31, wid = t >> 5;
    if (lane == 0) { sr0[wid] = mlp; sr1[wid] = mln; sr2[wid] = mc; }
    __syncthreads();
    if (t == 0) {
        double a0 = (double)sr0[0] + sr0[1] + sr0[2] + sr0[3];
        double a1 = (double)sr1[0] + sr1[1] + sr1[2] + sr1[3];
        int    a2 = sr2[0] + sr2[1] + sr2[2] + sr2[3];
        atomicAdd(&g_acc[0], a0);
        atomicAdd(&g_acc[1], a1);
        atomicAdd(&g_nmask, a2);
        __threadfence();
        unsigned old = atomicInc(&g_done, NBLK - 1);   // wraps -> replay-safe
        if (old == NBLK - 1) {
            // winner: all 256 blocks' contributions are in
            double p0 = atomicAdd(&g_acc[0], 0.0);
            double p1 = atomicAdd(&g_acc[1], 0.0);
            int    nm = atomicAdd(&g_nmask, 0);
            out[0] = (float)p0 / ((float)nm * 5.0f);   // W_POS = 1
            out[1] = (float)p1 / ((float)nm * 4.0f);   // W_NEG = 1
            // reset accumulators for the next graph replay (winner is last)
            g_acc[0] = 0.0; g_acc[1] = 0.0; g_nmask = 0;
            __threadfence();
        }
    }
}

// ---------------- launch: ONE kernel, fully independent blocks ----------------
extern "C" void kernel_launch(void* const* d_in, const int* in_sizes, int n_in,
                              void* d_out, int out_size) {
    const float* logits = (const float*)d_in[0];  // (2,19,128,128)
    const float* x_ema  = (const float*)d_in[1];  // (2,320,32,32)
    // d_in[2] = img_trg, unused by the reference.
    float* out = (float*)d_out;

    mono_k<<<NBLK, 128>>>(logits, x_ema, out);
}